// round 2
// baseline (speedup 1.0000x reference)
#include <cuda_runtime.h>
#include <cstdint>

#define CN   32
#define HID  256
#define K3   96
#define HH   256
#define WW   256
#define BB   8
#define NPIX (BB*HH*WW)          /* 524288 */
#define ROWS_PER_BLOCK 2
#define SMEM_FLOATS (HID*K3 + CN*HID + HID)   /* 24576+8192+256 = 33024 -> 132096 B */

__device__ float g_scratch[(size_t)NPIX * CN];

/* ---------------- packed f32x2 helpers (Blackwell FFMA2 path) ---------------- */
static __device__ __forceinline__ unsigned long long f2fma(unsigned long long a,
                                                           unsigned long long b,
                                                           unsigned long long c) {
    unsigned long long d;
    asm("fma.rn.f32x2 %0, %1, %2, %3;" : "=l"(d) : "l"(a), "l"(b), "l"(c));
    return d;
}
static __device__ __forceinline__ unsigned long long pk2(float a, float b) {
    unsigned long long r;
    asm("mov.b64 %0, {%1, %2};" : "=l"(r) : "f"(a), "f"(b));
    return r;
}
static __device__ __forceinline__ float2 up2(unsigned long long v) {
    float2 r;
    asm("mov.b64 {%0, %1}, %2;" : "=f"(r.x), "=f"(r.y) : "l"(v));
    return r;
}

/* ---------------- JAX threefry2x32 block (20 rounds) ---------------- */
static __device__ __forceinline__ uint2 threefry(uint32_t k0, uint32_t k1,
                                                 uint32_t x0, uint32_t x1) {
    uint32_t ks2 = k0 ^ k1 ^ 0x1BD11BDAu;
    x0 += k0; x1 += k1;
#define TF_R(r) { x0 += x1; x1 = __funnelshift_l(x1, x1, (r)); x1 ^= x0; }
    TF_R(13) TF_R(15) TF_R(26) TF_R(6)   x0 += k1;  x1 += ks2 + 1u;
    TF_R(17) TF_R(29) TF_R(16) TF_R(24)  x0 += ks2; x1 += k0  + 2u;
    TF_R(13) TF_R(15) TF_R(26) TF_R(6)   x0 += k0;  x1 += k1  + 3u;
    TF_R(17) TF_R(29) TF_R(16) TF_R(24)  x0 += k1;  x1 += ks2 + 4u;
    TF_R(13) TF_R(15) TF_R(26) TF_R(6)   x0 += ks2; x1 += k0  + 5u;
#undef TF_R
    return make_uint2(x0, x1);
}

/* ---------------- fused NCA step ---------------- */
extern "C" __global__ void __launch_bounds__(256, 1)
nca_step(const float* __restrict__ xin, float* __restrict__ xout,
         const float* __restrict__ fc0w, const float* __restrict__ fc0b,
         const float* __restrict__ fc1w, const int* __restrict__ stepsPtr,
         int stepIdx)
{
    const int tid = threadIdx.x;
    const int S = *stepsPtr;                     /* uniform across grid */
    const int rowBase = blockIdx.x * ROWS_PER_BLOCK;

    if (stepIdx >= S) {                          /* identity pass-through */
        #pragma unroll
        for (int r = 0; r < ROWS_PER_BLOCK; ++r) {
            size_t pix = (size_t)(rowBase + r) * WW + tid;
            const float4* s = (const float4*)(xin + pix * CN);
            float4* d = (float4*)(xout + pix * CN);
            #pragma unroll
            for (int q = 0; q < 8; ++q) d[q] = s[q];
        }
        return;
    }

    extern __shared__ float smem[];
    float* sW0 = smem;                 /* [256][96]  row-major copy of fc0_w */
    float* sW1 = sW0 + HID * K3;       /* [32][256]  row-major copy of fc1_w */
    float* sB  = sW1 + CN * HID;       /* [256] */

    {   /* coalesced, conflict-free weight staging */
        const float4* s0 = (const float4*)fc0w;  float4* d0 = (float4*)sW0;
        #pragma unroll
        for (int i = tid; i < HID * K3 / 4; i += 256) d0[i] = s0[i];
        const float4* s1 = (const float4*)fc1w;  float4* d1 = (float4*)sW1;
        #pragma unroll
        for (int i = tid; i < CN * HID / 4; i += 256) d1[i] = s1[i];
        if (tid < HID) sB[tid] = fc0b[tid];
    }
    __syncthreads();

    /* folded key for this step: fold_in(key(42), step) */
    const uint2 fk = threefry(0u, 42u, 0u, (uint32_t)stepIdx);

    #pragma unroll 1
    for (int r = 0; r < ROWS_PER_BLOCK; ++r) {
        const int row = rowBase + r;             /* row = b*256 + h */
        const int h = row & (HH - 1);
        const int w = tid;
        const float* pc = xin + ((size_t)row * WW + w) * CN;

        const bool hu = (h > 0), hd = (h < HH - 1);
        const bool wl = (w > 0), wr = (w < WW - 1);
        const int RU = -WW * CN, RD = WW * CN, CL = -CN, CR = CN;

        /* ---- perceive: y2[0..15]=x, y2[16..31]=dx(KX), y2[32..47]=dy(KY), packed pairs ---- */
        unsigned long long y2[48];
        #pragma unroll
        for (int cg = 0; cg < 8; ++cg) {
            const int oc = cg * 4;
            const float4 z = make_float4(0.f, 0.f, 0.f, 0.f);
            float4 c11 =              *(const float4*)(pc + oc);
            float4 m00 = (hu && wl) ? *(const float4*)(pc + RU + CL + oc) : z;
            float4 m01 =  hu        ? *(const float4*)(pc + RU      + oc) : z;
            float4 m02 = (hu && wr) ? *(const float4*)(pc + RU + CR + oc) : z;
            float4 m10 =  wl        ? *(const float4*)(pc + CL      + oc) : z;
            float4 m12 =  wr        ? *(const float4*)(pc + CR      + oc) : z;
            float4 m20 = (hd && wl) ? *(const float4*)(pc + RD + CL + oc) : z;
            float4 m21 =  hd        ? *(const float4*)(pc + RD      + oc) : z;
            float4 m22 = (hd && wr) ? *(const float4*)(pc + RD + CR + oc) : z;

            /* KX = [[-1,-2,-1],[0,0,0],[1,2,1]]/8 ; KY = [[-1,0,1],[-2,0,2],[-1,0,1]]/8 */
            float dx0 = 0.125f * ((m20.x - m00.x) + 2.f * (m21.x - m01.x) + (m22.x - m02.x));
            float dx1 = 0.125f * ((m20.y - m00.y) + 2.f * (m21.y - m01.y) + (m22.y - m02.y));
            float dx2 = 0.125f * ((m20.z - m00.z) + 2.f * (m21.z - m01.z) + (m22.z - m02.z));
            float dx3 = 0.125f * ((m20.w - m00.w) + 2.f * (m21.w - m01.w) + (m22.w - m02.w));
            float dy0 = 0.125f * ((m02.x - m00.x) + 2.f * (m12.x - m10.x) + (m22.x - m20.x));
            float dy1 = 0.125f * ((m02.y - m00.y) + 2.f * (m12.y - m10.y) + (m22.y - m20.y));
            float dy2 = 0.125f * ((m02.z - m00.z) + 2.f * (m12.z - m10.z) + (m22.z - m20.z));
            float dy3 = 0.125f * ((m02.w - m00.w) + 2.f * (m12.w - m10.w) + (m22.w - m20.w));

            y2[2*cg]        = pk2(c11.x, c11.y);
            y2[2*cg + 1]    = pk2(c11.z, c11.w);
            y2[16 + 2*cg]   = pk2(dx0, dx1);
            y2[16 + 2*cg+1] = pk2(dx2, dx3);
            y2[32 + 2*cg]   = pk2(dy0, dy1);
            y2[32 + 2*cg+1] = pk2(dy2, dy3);
        }

        /* ---- MLP: h = W0 y + b (pair over k), d = W1 h (pair over o) ---- */
        unsigned long long dacc[CN];
        #pragma unroll
        for (int c = 0; c < CN; ++c) dacc[c] = 0ull;

        #pragma unroll 1
        for (int og = 0; og < HID; og += 8) {
            unsigned long long hp[8];
            #pragma unroll
            for (int t = 0; t < 8; ++t) hp[t] = 0ull;

            #pragma unroll
            for (int t = 0; t < 8; ++t) {
                const ulonglong2* wrow = (const ulonglong2*)(sW0 + (og + t) * K3);
                #pragma unroll
                for (int j = 0; j < 24; ++j) {
                    ulonglong2 wv = wrow[j];                 /* LDS.128 broadcast */
                    hp[t] = f2fma(y2[2*j],     wv.x, hp[t]);
                    hp[t] = f2fma(y2[2*j + 1], wv.y, hp[t]);
                }
            }
            unsigned long long hpair[4];
            #pragma unroll
            for (int p = 0; p < 4; ++p) {
                float2 a = up2(hp[2*p]);
                float2 b = up2(hp[2*p + 1]);
                hpair[p] = pk2(a.x + a.y + sB[og + 2*p],
                               b.x + b.y + sB[og + 2*p + 1]);
            }
            #pragma unroll
            for (int p = 0; p < 4; ++p) {
                const float* w1 = sW1 + og + 2*p;
                #pragma unroll
                for (int c = 0; c < CN; ++c) {
                    unsigned long long wv = *(const unsigned long long*)(w1 + c * HID);
                    dacc[c] = f2fma(hpair[p], wv, dacc[c]);
                }
            }
        }

        /* ---- fire mask: JAX threefry (partitionable path), uniform>0.5 ---- */
        const uint32_t j32 = (uint32_t)row * WW + (uint32_t)w;
        uint2 rb = threefry(fk.x, fk.y, 0u, j32);
        uint32_t bits = rb.x ^ rb.y;
        float u = __uint_as_float((bits >> 9) | 0x3f800000u) - 1.0f;
        float m = (u > 0.5f) ? 1.0f : 0.0f;

        /* ---- update + store ---- */
        float outv[CN];
        #pragma unroll
        for (int c = 0; c < CN; ++c) {
            float2 dp = up2(dacc[c]);
            float dsum = dp.x + dp.y;
            float2 xv = up2(y2[c >> 1]);
            float xc = (c & 1) ? xv.y : xv.x;
            float t = xc + dsum * m;
            float sg = 1.0f / (1.0f + expf(-t));
            outv[c] = (c < 3) ? xc : sg;
        }
        float4* dstp = (float4*)(xout + ((size_t)row * WW + w) * CN);
        #pragma unroll
        for (int q = 0; q < 8; ++q)
            dstp[q] = make_float4(outv[4*q], outv[4*q+1], outv[4*q+2], outv[4*q+3]);
    }
}

/* ---------------- launch ---------------- */
extern "C" void kernel_launch(void* const* d_in, const int* in_sizes, int n_in,
                              void* d_out, int out_size)
{
    const float* x    = (const float*)d_in[0];
    const float* fc0w = (const float*)d_in[1];
    const float* fc0b = (const float*)d_in[2];
    const float* fc1w = (const float*)d_in[3];
    const int*   st   = (const int*)d_in[4];
    float* out = (float*)d_out;

    float* scratch = nullptr;
    cudaGetSymbolAddress((void**)&scratch, g_scratch);

    const int smemBytes = SMEM_FLOATS * (int)sizeof(float);
    cudaFuncSetAttribute((const void*)nca_step,
                         cudaFuncAttributeMaxDynamicSharedMemorySize, smemBytes);

    dim3 grid(NPIX / WW / ROWS_PER_BLOCK);   /* 1024 */
    dim3 block(256);
    nca_step<<<grid, block, smemBytes>>>(x,       scratch, fc0w, fc0b, fc1w, st, 0);
    nca_step<<<grid, block, smemBytes>>>(scratch, out,     fc0w, fc0b, fc1w, st, 1);
}